// round 9
// baseline (speedup 1.0000x reference)
#include <cuda_runtime.h>
#include <cuda_bf16.h>

// ---------------------------------------------------------------------------
// Net_4174708212167: 4-qubit circuit per 2x2 patch + MLP, fully fused.
// One block per image, 512 threads, 2 threads per patch (statevector split
// on qubit 3). Local amp index l in [0,8): global idx = (l<<1) | b, where
// b = threadIdx.x & 1. Local masks: q0->4, q1->2, q2->1; q3 is the split bit.
// ---------------------------------------------------------------------------

#define NPATCH 196
#define FEAT_DIM 784
#define PRE 12               // prefetched float2s per thread for FC1
#define FULLMASK 0xFFFFFFFFu

// --- local 1-qubit gates on 8-amplitude half-statevector -------------------
__device__ __forceinline__ void gate_u8(float* re, float* im, int m, const float* u) {
    const float4* u4 = reinterpret_cast<const float4*>(u);
    float4 ua = u4[0];           // u00r u00i u01r u01i
    float4 ub = u4[1];           // u10r u10i u11r u11i
#pragma unroll
    for (int l = 0; l < 8; ++l) {
        if (l & m) continue;
        int k = l | m;
        float jr = re[l], ji = im[l], kr = re[k], ki = im[k];
        re[l] = ua.x * jr - ua.y * ji + ua.z * kr - ua.w * ki;
        im[l] = ua.x * ji + ua.y * jr + ua.z * ki + ua.w * kr;
        re[k] = ub.x * jr - ub.y * ji + ub.z * kr - ub.w * ki;
        im[k] = ub.x * ji + ub.y * jr + ub.z * ki + ub.w * kr;
    }
}

__device__ __forceinline__ void gate_rx8(float* re, float* im, int m, float c, float s) {
#pragma unroll
    for (int l = 0; l < 8; ++l) {
        if (l & m) continue;
        int k = l | m;
        float jr = re[l], ji = im[l], kr = re[k], ki = im[k];
        re[l] = c * jr + s * ki;
        im[l] = c * ji - s * kr;
        re[k] = c * kr + s * ji;
        im[k] = c * ki - s * jr;
    }
}

// Rx on the split qubit: mine_new = c*mine - i*s*partner  (matrix symmetric)
__device__ __forceinline__ void cross_rx(float* re, float* im, float c, float s) {
    float pr[8], pim[8];
#pragma unroll
    for (int l = 0; l < 8; ++l) {
        pr[l]  = __shfl_xor_sync(FULLMASK, re[l], 1);
        pim[l] = __shfl_xor_sync(FULLMASK, im[l], 1);
    }
#pragma unroll
    for (int l = 0; l < 8; ++l) {
        float r = re[l], i = im[l];
        re[l] = c * r + s * pim[l];
        im[l] = c * i - s * pr[l];
    }
}

// General U on the split qubit: mine_new = U[b][b]*mine + U[b][1-b]*partner
__device__ __forceinline__ void cross_u(float* re, float* im, const float* u, int b) {
    const float4* u4 = reinterpret_cast<const float4*>(u);
    float4 row = u4[b];                         // row b: (U[b][0], U[b][1])
    float dr = b ? row.z : row.x, di = b ? row.w : row.y;   // diag col b
    float orr = b ? row.x : row.z, oi = b ? row.y : row.w;  // off  col 1-b
    float pr[8], pim[8];
#pragma unroll
    for (int l = 0; l < 8; ++l) {
        pr[l]  = __shfl_xor_sync(FULLMASK, re[l], 1);
        pim[l] = __shfl_xor_sync(FULLMASK, im[l], 1);
    }
#pragma unroll
    for (int l = 0; l < 8; ++l) {
        float r = re[l], i = im[l];
        re[l] = dr * r - di * i + orr * pr[l] - oi * pim[l];
        im[l] = dr * i + di * r + orr * pim[l] + oi * pr[l];
    }
}

__device__ __forceinline__ void swapf(float& a, float& b) { float t = a; a = b; b = t; }

// ---------------------------------------------------------------------------
__global__ void __launch_bounds__(512, 1)
fused_kernel(const float* __restrict__ x, const float* __restrict__ wts,
             const float* __restrict__ w1, const float* __restrict__ b1,
             const float* __restrict__ w2, const float* __restrict__ b2,
             float* __restrict__ out) {
    __shared__ __align__(16) float sx[FEAT_DIM];   // image pixels
    __shared__ __align__(16) float su[20][8];      // composed U per (layer,qubit)
    __shared__ __align__(16) float sf[FEAT_DIM];   // circuit features
    __shared__ float spart[512];                   // FC1 partial sums
    __shared__ float sh[64];                       // FC1 activations

    const int bid = blockIdx.x;
    const int t = threadIdx.x;

    // FC1 work assignment (phase 1b prefetch + phase 3): 8-way split-K
    const int j  = t & 63;         // output neuron
    const int c8 = t >> 6;         // K-chunk (98 floats = 49 float2)
    const float2* w2p = reinterpret_cast<const float2*>(w1 + j * FEAT_DIM + c8 * 98);

    // ---- phase 1: stage image + build composed gate matrices ----
    {
        const float4* img4 = reinterpret_cast<const float4*>(x + bid * FEAT_DIM);
        float4* sx4 = reinterpret_cast<float4*>(sx);
        if (t < FEAT_DIM / 4) sx4[t] = img4[t];
    }
    if (t < 20) {
        int l = t >> 2, qq = t & 3;
        float a  = wts[l * 12 + qq];
        float bb = wts[l * 12 + 4 + qq];
        float c  = wts[l * 12 + 8 + qq];
        float sa, ca, sb, cb, sc, cc;
        sincosf(0.5f * a,  &sa, &ca);
        sincosf(0.5f * bb, &sb, &cb);
        sincosf(0.5f * c,  &sc, &cc);
        // M = Rz(b)*Ry(a)
        float m00r =  cb * ca, m00i = -sb * ca;
        float m01r = -cb * sa, m01i =  sb * sa;
        float m10r =  cb * sa, m10i =  sb * sa;
        float m11r =  cb * ca, m11i =  sb * ca;
        // U = Ry(c)*M
        su[t][0] = cc * m00r - sc * m10r;  su[t][1] = cc * m00i - sc * m10i;
        su[t][2] = cc * m01r - sc * m11r;  su[t][3] = cc * m01i - sc * m11i;
        su[t][4] = sc * m00r + cc * m10r;  su[t][5] = sc * m00i + cc * m10i;
        su[t][6] = sc * m01r + cc * m11r;  su[t][7] = sc * m01i + cc * m11i;
    }

    // ---- phase 1b: prefetch FC1 weight chunk (hidden under circuit) ----
    float2 wpre[PRE];
#pragma unroll
    for (int k = 0; k < PRE; ++k) wpre[k] = w2p[k];

    __syncthreads();

    // ---- phase 2: 2 threads per patch; ALL threads execute (clamped patch)
    //      so shfl masks are uniform; only t<392 store features ----
    {
        int p = t >> 1; if (p > NPATCH - 1) p = NPATCH - 1;
        const int b = t & 1;
        int pi = p / 14;
        int pj = p - pi * 14;
        float a0 = sx[(2 * pi) * 28 + 2 * pj];
        float a1 = sx[(2 * pi) * 28 + 2 * pj + 1];
        float a2 = sx[(2 * pi + 1) * 28 + 2 * pj];
        float a3 = sx[(2 * pi + 1) * 28 + 2 * pj + 1];

        float re[8], im[8];
#pragma unroll
        for (int i = 0; i < 8; ++i) { re[i] = 0.f; im[i] = 0.f; }
        if (b == 0) re[0] = 1.f;

        float c, s;
        sincospif(a0, &s, &c); gate_rx8(re, im, 4, c, s);   // q0
        sincospif(a1, &s, &c); gate_rx8(re, im, 2, c, s);   // q1
        sincospif(a2, &s, &c); gate_rx8(re, im, 1, c, s);   // q2
        sincospif(a3, &s, &c); cross_rx(re, im, c, s);      // q3 (split)

#pragma unroll
        for (int layer = 0; layer < 5; ++layer) {
            gate_u8(re, im, 4, su[layer * 4 + 0]);          // q0
            gate_u8(re, im, 2, su[layer * 4 + 1]);          // q1
            gate_u8(re, im, 1, su[layer * 4 + 2]);          // q2
            cross_u(re, im, su[layer * 4 + 3], b);          // q3
            if (layer < 4) {
                // CNOT(0,1): local bit4 controls swap of bit2
                swapf(re[4], re[6]); swapf(im[4], im[6]);
                swapf(re[5], re[7]); swapf(im[5], im[7]);
                // CNOT(1,2): local bit2 controls swap of bit1
                swapf(re[2], re[3]); swapf(im[2], im[3]);
                swapf(re[6], re[7]); swapf(im[6], im[7]);
                // CNOT(2,3): local bit1=1 amps exchange with partner thread
#pragma unroll
                for (int l = 1; l < 8; l += 2) {
                    re[l] = __shfl_xor_sync(FULLMASK, re[l], 1);
                    im[l] = __shfl_xor_sync(FULLMASK, im[l], 1);
                }
                // CNOT(3,0): split bit (b) controls swap of local bit4
#pragma unroll
                for (int l = 0; l < 4; ++l) {
                    float r0 = re[l], r1 = re[l + 4];
                    re[l] = b ? r1 : r0;  re[l + 4] = b ? r0 : r1;
                    float i0 = im[l], i1 = im[l + 4];
                    im[l] = b ? i1 : i0;  im[l + 4] = b ? i0 : i1;
                }
            }
        }

        // <Z_q>: local partial sums, combined across the pair via shfl
        float s0 = 0.f, s1 = 0.f, s2 = 0.f, s3 = 0.f;
#pragma unroll
        for (int l = 0; l < 8; ++l) {
            float pr = re[l] * re[l] + im[l] * im[l];
            s0 += (l & 4) ? -pr : pr;
            s1 += (l & 2) ? -pr : pr;
            s2 += (l & 1) ? -pr : pr;
            s3 += pr;
        }
        if (b) s3 = -s3;
        s0 += __shfl_xor_sync(FULLMASK, s0, 1);
        s1 += __shfl_xor_sync(FULLMASK, s1, 1);
        s2 += __shfl_xor_sync(FULLMASK, s2, 1);
        s3 += __shfl_xor_sync(FULLMASK, s3, 1);

        if (t < 2 * NPATCH) {
            if (b == 0) { sf[p * 4 + 0] = s0; sf[p * 4 + 1] = s1; }
            else        { sf[p * 4 + 2] = s2; sf[p * 4 + 3] = s3; }
        }
    }
    __syncthreads();

    // ---- phase 3: FC1 (64 x 784), 8-way split-K, float2 ----
    {
        const float2* f2 = reinterpret_cast<const float2*>(sf + c8 * 98);
        float acc = 0.f;
#pragma unroll
        for (int k = 0; k < PRE; ++k) {
            float2 wv = wpre[k];
            float2 fv = f2[k];
            acc += fv.x * wv.x + fv.y * wv.y;
        }
#pragma unroll
        for (int k = PRE; k < 49; ++k) {
            float2 wv = w2p[k];
            float2 fv = f2[k];
            acc += fv.x * wv.x + fv.y * wv.y;
        }
        spart[t] = acc;
    }
    __syncthreads();
    if (t < 64) {
        float acc = b1[t];
#pragma unroll
        for (int i = 0; i < 8; ++i) acc += spart[t + 64 * i];
        sh[t] = fmaxf(acc, 0.f);
    }
    __syncthreads();

    // ---- phase 4: FC2 (10 x 64) ----
    if (t < 10) {
        const float* w = w2 + t * 64;
        float acc = b2[t];
#pragma unroll
        for (int k = 0; k < 64; ++k) acc += sh[k] * w[k];
        out[bid * 10 + t] = acc;
    }
}

// ---------------------------------------------------------------------------
extern "C" void kernel_launch(void* const* d_in, const int* in_sizes, int n_in,
                              void* d_out, int out_size) {
    const float* x     = (const float*)d_in[0];
    const float* wts   = (const float*)d_in[1];
    const float* fc1_w = (const float*)d_in[2];
    const float* fc1_b = (const float*)d_in[3];
    const float* fc2_w = (const float*)d_in[4];
    const float* fc2_b = (const float*)d_in[5];
    float* out = (float*)d_out;

    int B = in_sizes[0] / FEAT_DIM;   // 128

    fused_kernel<<<B, 512>>>(x, wts, fc1_w, fc1_b, fc2_w, fc2_b, out);
}

// round 10
// speedup vs baseline: 1.3907x; 1.3907x over previous
#include <cuda_runtime.h>
#include <cuda_bf16.h>

// ---------------------------------------------------------------------------
// Net_4174708212167: 4-qubit circuit per 2x2 patch + MLP, fully fused.
// Key identity: circuit = Rx-encoding (tensor-product state, real vector
// rv[16] x column phases (-i)^popcount) followed by a FIXED 16x16 unitary W
// (5 YZY layers + CNOT rings, data-independent). Per block:
//  (1) stage image, build 20 composed SU(2) gates, prefetch FC1 weights
//  (A) evolve 16 basis columns through the gate chain (32-lane split rep,
//      replicated across all warps; warp 0 stores) -> W' in shared with
//      column phases folded in
//  (2) per patch (1 thread): rv[16] tensor product, f = W'rv (2 real
//      16x16 matvecs), <Z_q> from |f|^2 -> features
//  (3) FC1 64x784 split-K 4 + ReLU, (4) FC2 10x64
// ---------------------------------------------------------------------------

#define NPATCH 196
#define FEAT_DIM 784
#define PRE 8                // prefetched float4s per thread for FC1
#define FULLMASK 0xFFFFFFFFu

// --- local 1-qubit gate on 8-amplitude half-statevector (split rep) --------
__device__ __forceinline__ void gate_u8(float* re, float* im, int m, const float* u) {
    const float4* u4 = reinterpret_cast<const float4*>(u);
    float4 ua = u4[0];           // u00r u00i u01r u01i
    float4 ub = u4[1];           // u10r u10i u11r u11i
#pragma unroll
    for (int l = 0; l < 8; ++l) {
        if (l & m) continue;
        int k = l | m;
        float jr = re[l], ji = im[l], kr = re[k], ki = im[k];
        re[l] = ua.x * jr - ua.y * ji + ua.z * kr - ua.w * ki;
        im[l] = ua.x * ji + ua.y * jr + ua.z * ki + ua.w * kr;
        re[k] = ub.x * jr - ub.y * ji + ub.z * kr - ub.w * ki;
        im[k] = ub.x * ji + ub.y * jr + ub.z * ki + ub.w * kr;
    }
}

// General U on the split qubit: mine_new = U[b][b]*mine + U[b][1-b]*partner
__device__ __forceinline__ void cross_u(float* re, float* im, const float* u, int b) {
    const float4* u4 = reinterpret_cast<const float4*>(u);
    float4 row = u4[b];                         // row b of U
    float dr = b ? row.z : row.x, di = b ? row.w : row.y;   // diag element
    float orr = b ? row.x : row.z, oi = b ? row.y : row.w;  // off-diag
    float pr[8], pim[8];
#pragma unroll
    for (int l = 0; l < 8; ++l) {
        pr[l]  = __shfl_xor_sync(FULLMASK, re[l], 1);
        pim[l] = __shfl_xor_sync(FULLMASK, im[l], 1);
    }
#pragma unroll
    for (int l = 0; l < 8; ++l) {
        float r = re[l], i = im[l];
        re[l] = dr * r - di * i + orr * pr[l] - oi * pim[l];
        im[l] = dr * i + di * r + orr * pim[l] + oi * pr[l];
    }
}

__device__ __forceinline__ void swapf(float& a, float& b) { float t = a; a = b; b = t; }

// ---------------------------------------------------------------------------
__global__ void __launch_bounds__(256, 1)
fused_kernel(const float* __restrict__ x, const float* __restrict__ wts,
             const float* __restrict__ w1, const float* __restrict__ b1,
             const float* __restrict__ w2, const float* __restrict__ b2,
             float* __restrict__ out) {
    __shared__ __align__(16) float sx[FEAT_DIM];   // image pixels
    __shared__ __align__(16) float su[20][8];      // composed U per (layer,qubit)
    __shared__ __align__(16) float swr[16][16];    // Re W' (phase-folded), [col][row]
    __shared__ __align__(16) float swi[16][16];    // Im W'
    __shared__ __align__(16) float sf[FEAT_DIM];   // circuit features
    __shared__ float spart[256];                   // FC1 partial sums
    __shared__ float sh[64];                       // FC1 activations

    const int bid = blockIdx.x;
    const int t = threadIdx.x;

    // FC1 work assignment (phases 1b and 3): 4-way split-K, float4
    const int j = t & 63;          // output neuron
    const int q = t >> 6;          // K-quarter (196 floats = 49 float4)
    const float4* w4 = reinterpret_cast<const float4*>(w1 + j * FEAT_DIM + q * NPATCH);

    // ---- phase 1: stage image + build composed gate matrices ----
    {
        const float4* img4 = reinterpret_cast<const float4*>(x + bid * FEAT_DIM);
        float4* sx4 = reinterpret_cast<float4*>(sx);
        for (int i = t; i < FEAT_DIM / 4; i += 256) sx4[i] = img4[i];
    }
    if (t < 20) {
        int l = t >> 2, qq = t & 3;
        float a  = wts[l * 12 + qq];
        float bb = wts[l * 12 + 4 + qq];
        float c  = wts[l * 12 + 8 + qq];
        float sa, ca, sb, cb, sc, cc;
        sincosf(0.5f * a,  &sa, &ca);
        sincosf(0.5f * bb, &sb, &cb);
        sincosf(0.5f * c,  &sc, &cc);
        // M = Rz(b)*Ry(a)
        float m00r =  cb * ca, m00i = -sb * ca;
        float m01r = -cb * sa, m01i =  sb * sa;
        float m10r =  cb * sa, m10i =  sb * sa;
        float m11r =  cb * ca, m11i =  sb * ca;
        // U = Ry(c)*M
        su[t][0] = cc * m00r - sc * m10r;  su[t][1] = cc * m00i - sc * m10i;
        su[t][2] = cc * m01r - sc * m11r;  su[t][3] = cc * m01i - sc * m11i;
        su[t][4] = sc * m00r + cc * m10r;  su[t][5] = sc * m00i + cc * m10i;
        su[t][6] = sc * m01r + cc * m11r;  su[t][7] = sc * m01i + cc * m11i;
    }

    // ---- phase 1b: prefetch FC1 weight chunk (hidden under circuit) ----
    float4 wpre[PRE];
#pragma unroll
    for (int k = 0; k < PRE; ++k) wpre[k] = w4[k];

    __syncthreads();

    // ---- phase A: build W' (16x16, column phases folded) ----
    // Split representation: thread pair (even,odd lanes) evolves basis column
    // c = (t>>1)&15; local amp l (bits q0->4,q1->2,q2->1), split bit = q3 = t&1.
    // All 256 threads run (8 redundant copies keep shfl masks uniform);
    // only t<32 stores.
    {
        const int c = (t >> 1) & 15;
        const int b = t & 1;
        float re[8], im[8];
#pragma unroll
        for (int i = 0; i < 8; ++i) { re[i] = 0.f; im[i] = 0.f; }
        if ((c & 1) == b) re[c >> 1] = 1.f;

#pragma unroll
        for (int layer = 0; layer < 5; ++layer) {
            gate_u8(re, im, 4, su[layer * 4 + 0]);          // q0
            gate_u8(re, im, 2, su[layer * 4 + 1]);          // q1
            gate_u8(re, im, 1, su[layer * 4 + 2]);          // q2
            cross_u(re, im, su[layer * 4 + 3], b);          // q3
            if (layer < 4) {
                // CNOT(0,1): local bit4 controls swap of bit2
                swapf(re[4], re[6]); swapf(im[4], im[6]);
                swapf(re[5], re[7]); swapf(im[5], im[7]);
                // CNOT(1,2): local bit2 controls swap of bit1
                swapf(re[2], re[3]); swapf(im[2], im[3]);
                swapf(re[6], re[7]); swapf(im[6], im[7]);
                // CNOT(2,3): local bit1=1 amps exchange with partner thread
#pragma unroll
                for (int l = 1; l < 8; l += 2) {
                    re[l] = __shfl_xor_sync(FULLMASK, re[l], 1);
                    im[l] = __shfl_xor_sync(FULLMASK, im[l], 1);
                }
                // CNOT(3,0): split bit (b) controls swap of local bit4
#pragma unroll
                for (int l = 0; l < 4; ++l) {
                    float r0 = re[l], r1 = re[l + 4];
                    re[l] = b ? r1 : r0;  re[l + 4] = b ? r0 : r1;
                    float i0 = im[l], i1 = im[l + 4];
                    im[l] = b ? i1 : i0;  im[l + 4] = b ? i0 : i1;
                }
            }
        }

        if (t < 32) {
            int k = __popc(c) & 3;    // column phase (-i)^k
#pragma unroll
            for (int l = 0; l < 8; ++l) {
                int r = (l << 1) | b;
                float fr = re[l], fi = im[l], gr, gi;
                if      (k == 0) { gr =  fr; gi =  fi; }
                else if (k == 1) { gr =  fi; gi = -fr; }
                else if (k == 2) { gr = -fr; gi = -fi; }
                else             { gr = -fi; gi =  fr; }
                swr[c][r] = gr;
                swi[c][r] = gi;
            }
        }
    }
    __syncthreads();

    // ---- phase 2: per-patch encoding + 16x16 matvec + <Z> epilogue ----
    if (t < NPATCH) {
        int pi = t / 14;
        int pj = t - pi * 14;
        float a0 = sx[(2 * pi) * 28 + 2 * pj];
        float a1 = sx[(2 * pi) * 28 + 2 * pj + 1];
        float a2 = sx[(2 * pi + 1) * 28 + 2 * pj];
        float a3 = sx[(2 * pi + 1) * 28 + 2 * pj + 1];

        float c0, s0, c1, s1, c2, s2, c3, s3;
        sincospif(a0, &s0, &c0);
        sincospif(a1, &s1, &c1);
        sincospif(a2, &s2, &c2);
        sincospif(a3, &s3, &c3);

        // rv[idx] = prod_q (bit_q ? s_q : c_q); idx bits: q0=8,q1=4,q2=2,q3=1
        float p01[4] = { c0 * c1, c0 * s1, s0 * c1, s0 * s1 };
        float p23[4] = { c2 * c3, c2 * s3, s2 * c3, s2 * s3 };
        float rv[16];
#pragma unroll
        for (int i = 0; i < 4; ++i)
#pragma unroll
            for (int jj = 0; jj < 4; ++jj)
                rv[i * 4 + jj] = p01[i] * p23[jj];

        // f = W' rv (two real 16x16 matvecs; W' columns broadcast via LDS.128)
        float fr[16], fi[16];
#pragma unroll
        for (int r = 0; r < 16; ++r) { fr[r] = 0.f; fi[r] = 0.f; }
#pragma unroll
        for (int c = 0; c < 16; ++c) {
            float av = rv[c];
            const float4* wr4 = reinterpret_cast<const float4*>(swr[c]);
            const float4* wi4 = reinterpret_cast<const float4*>(swi[c]);
#pragma unroll
            for (int rr = 0; rr < 4; ++rr) {
                float4 wr = wr4[rr];
                float4 wi = wi4[rr];
                fr[rr * 4 + 0] += av * wr.x;  fi[rr * 4 + 0] += av * wi.x;
                fr[rr * 4 + 1] += av * wr.y;  fi[rr * 4 + 1] += av * wi.y;
                fr[rr * 4 + 2] += av * wr.z;  fi[rr * 4 + 2] += av * wi.z;
                fr[rr * 4 + 3] += av * wr.w;  fi[rr * 4 + 3] += av * wi.w;
            }
        }

        // <Z_q> from |f|^2 (row bits: q0=8, q1=4, q2=2, q3=1)
        float e0 = 0.f, e1 = 0.f, e2 = 0.f, e3 = 0.f;
#pragma unroll
        for (int r = 0; r < 16; ++r) {
            float pr = fr[r] * fr[r] + fi[r] * fi[r];
            e0 += (r & 8) ? -pr : pr;
            e1 += (r & 4) ? -pr : pr;
            e2 += (r & 2) ? -pr : pr;
            e3 += (r & 1) ? -pr : pr;
        }
        sf[t * 4 + 0] = e0;
        sf[t * 4 + 1] = e1;
        sf[t * 4 + 2] = e2;
        sf[t * 4 + 3] = e3;
    }
    __syncthreads();

    // ---- phase 3: FC1 (64 x 784), 4-way split-K, float4 ----
    {
        const float4* f4 = reinterpret_cast<const float4*>(sf + q * NPATCH);
        float acc = 0.f;
#pragma unroll
        for (int k = 0; k < PRE; ++k) {
            float4 wv = wpre[k];
            float4 fv = f4[k];
            acc += fv.x * wv.x + fv.y * wv.y + fv.z * wv.z + fv.w * wv.w;
        }
#pragma unroll
        for (int k = PRE; k < NPATCH / 4; ++k) {
            float4 wv = w4[k];
            float4 fv = f4[k];
            acc += fv.x * wv.x + fv.y * wv.y + fv.z * wv.z + fv.w * wv.w;
        }
        spart[t] = acc;
    }
    __syncthreads();
    if (t < 64) {
        float acc = spart[t] + spart[64 + t] + spart[128 + t] + spart[192 + t] + b1[t];
        sh[t] = fmaxf(acc, 0.f);
    }
    __syncthreads();

    // ---- phase 4: FC2 (10 x 64) ----
    if (t < 10) {
        const float* w = w2 + t * 64;
        float acc = b2[t];
#pragma unroll
        for (int k = 0; k < 64; ++k) acc += sh[k] * w[k];
        out[bid * 10 + t] = acc;
    }
}

// ---------------------------------------------------------------------------
extern "C" void kernel_launch(void* const* d_in, const int* in_sizes, int n_in,
                              void* d_out, int out_size) {
    const float* x     = (const float*)d_in[0];
    const float* wts   = (const float*)d_in[1];
    const float* fc1_w = (const float*)d_in[2];
    const float* fc1_b = (const float*)d_in[3];
    const float* fc2_w = (const float*)d_in[4];
    const float* fc2_b = (const float*)d_in[5];
    float* out = (float*)d_out;

    int B = in_sizes[0] / FEAT_DIM;   // 128

    fused_kernel<<<B, 256>>>(x, wts, fc1_w, fc1_b, fc2_w, fc2_b, out);
}